// round 1
// baseline (speedup 1.0000x reference)
#include <cuda_runtime.h>
#include <cuda_bf16.h>
#include <math.h>

// Problem constants
#define BB 8
#define NN 8192
#define CC 512
#define HH 8
#define DD 64
#define MM (BB * NN)   // 65536 rows

// ---------------- scratch (device globals; no allocation) ----------------
__device__ float g_Y[(size_t)MM * CC];        // 128 MB: Y = x @ Wqkv^T, layout (b,n,c)
__device__ float g_sumsq[BB * CC];            // per (b,c) sum over n of Y^2
__device__ float g_inv2[BB * CC];             // 1 / max(sumsq, 1e-24)
__device__ float g_Pi[(size_t)MM * HH];       // softmax over heads per row
__device__ float g_S1[BB * HH];               // sum_n Pi
__device__ float g_S2[BB * HH];               // sum_n Pi * (sum_d w^2)
__device__ float g_cf[(size_t)MM * HH];       // -Pi * attn
__device__ int   g_maskMode;                  // 0=int32, 1=byte, 2=float32

// ---------------- init + mask-format probe ----------------
__global__ void init_kernel(const int* __restrict__ maskI) {
    int idx = blockIdx.x * blockDim.x + threadIdx.x;
    // zero accumulators
    if (idx < BB * CC) g_sumsq[idx] = 0.0f;
    if (idx < BB * HH) { g_S1[idx] = 0.0f; g_S2[idx] = 0.0f; }
    // block 0 probes the mask dtype deterministically
    if (blockIdx.x == 0) {
        __shared__ int okInt, okFloat;
        if (threadIdx.x == 0) { okInt = 1; okFloat = 1; }
        __syncthreads();
        // scan first 1024 32-bit words (always in-bounds: >=65536 bytes exist)
        for (int i = threadIdx.x; i < 1024; i += blockDim.x) {
            unsigned int v = ((const unsigned int*)maskI)[i];
            if (!(v == 0u || v == 1u)) atomicAnd(&okInt, 0);
            if (!(v == 0u || v == 0x3F800000u)) atomicAnd(&okFloat, 0);
        }
        __syncthreads();
        if (threadIdx.x == 0) {
            g_maskMode = okInt ? 0 : (okFloat ? 2 : 1);
        }
    }
}

// ---------------- SGEMM (NT): C[m,n] = sum_k A[m,k]*B[n,k] ----------------
// BM=BN=128, BK=16, 256 threads, 8x8 microtile.
// APPLY=1: A is scaled per-element by cf[m][k>>6], and bias[n] added to C.
template <int APPLY>
__global__ void __launch_bounds__(256)
sgemm_nt(const float* __restrict__ A, const float* __restrict__ B,
         float* __restrict__ C, const float* __restrict__ cf,
         const float* __restrict__ bias) {
    __shared__ float As[16][128];
    __shared__ float Bs[16][128];

    const int bm = blockIdx.y * 128;
    const int bn = blockIdx.x * 128;
    const int tid = threadIdx.x;
    const int tx = tid & 15;   // 0..15  -> n microtile
    const int ty = tid >> 4;   // 0..15  -> m microtile

    float acc[8][8];
#pragma unroll
    for (int i = 0; i < 8; i++)
#pragma unroll
        for (int j = 0; j < 8; j++) acc[i][j] = 0.0f;

    for (int k0 = 0; k0 < CC; k0 += 16) {
#pragma unroll
        for (int i = 0; i < 2; i++) {
            int f = tid + i * 256;           // 0..511
            int row = f >> 2;                // 0..127
            int k4 = (f & 3) * 4;            // 0,4,8,12
            const float4 av = *(const float4*)(A + (size_t)(bm + row) * CC + k0 + k4);
            float c0 = av.x, c1 = av.y, c2 = av.z, c3 = av.w;
            if (APPLY) {
                float s = cf[(size_t)(bm + row) * HH + ((k0 + k4) >> 6)];
                c0 *= s; c1 *= s; c2 *= s; c3 *= s;
            }
            As[k4 + 0][row] = c0; As[k4 + 1][row] = c1;
            As[k4 + 2][row] = c2; As[k4 + 3][row] = c3;
            const float4 bv = *(const float4*)(B + (size_t)(bn + row) * CC + k0 + k4);
            Bs[k4 + 0][row] = bv.x; Bs[k4 + 1][row] = bv.y;
            Bs[k4 + 2][row] = bv.z; Bs[k4 + 3][row] = bv.w;
        }
        __syncthreads();
#pragma unroll
        for (int kk = 0; kk < 16; kk++) {
            float a[8], b[8];
#pragma unroll
            for (int i = 0; i < 4; i++) {
                ((float4*)a)[i >> 1 ? 1 : 0] = ((float4*)a)[0]; // placeholder avoided below
            }
            // vector loads from smem
            *(float4*)&a[0] = *(const float4*)&As[kk][ty * 8 + 0];
            *(float4*)&a[4] = *(const float4*)&As[kk][ty * 8 + 4];
            *(float4*)&b[0] = *(const float4*)&Bs[kk][tx * 8 + 0];
            *(float4*)&b[4] = *(const float4*)&Bs[kk][tx * 8 + 4];
#pragma unroll
            for (int i = 0; i < 8; i++)
#pragma unroll
                for (int j = 0; j < 8; j++) acc[i][j] = fmaf(a[i], b[j], acc[i][j]);
        }
        __syncthreads();
    }

#pragma unroll
    for (int i = 0; i < 8; i++) {
        int m = bm + ty * 8 + i;
#pragma unroll
        for (int j = 0; j < 8; j += 4) {
            int n = bn + tx * 8 + j;
            float4 v = make_float4(acc[i][j], acc[i][j + 1], acc[i][j + 2], acc[i][j + 3]);
            if (APPLY) {
                v.x += bias[n]; v.y += bias[n + 1];
                v.z += bias[n + 2]; v.w += bias[n + 3];
            }
            *(float4*)(C + (size_t)m * CC + n) = v;
        }
    }
}

// ---------------- column sum-of-squares over n, partial per block ----------------
// grid: (C/128, B, 8)  -> block handles 128 c's, one b, 1024-row n-slab
__global__ void __launch_bounds__(256) colnorm_accum() {
    __shared__ float s[256];
    const int cx = threadIdx.x & 127;
    const int ny = threadIdx.x >> 7;     // 0..1
    const int c0 = blockIdx.x * 128;
    const int b = blockIdx.y;
    const int n0 = blockIdx.z * 1024;
    const float* base = g_Y + ((size_t)b * NN) * CC + c0 + cx;
    float acc = 0.0f;
    for (int n = n0 + ny; n < n0 + 1024; n += 2) {
        float v = base[(size_t)n * CC];
        acc = fmaf(v, v, acc);
    }
    s[threadIdx.x] = acc;
    __syncthreads();
    if (threadIdx.x < 128) {
        float tot = s[threadIdx.x] + s[threadIdx.x + 128];
        atomicAdd(&g_sumsq[b * CC + c0 + cx], tot);
    }
}

__global__ void colnorm_finalize() {
    int idx = blockIdx.x * blockDim.x + threadIdx.x;
    if (idx < BB * CC) {
        float s = g_sumsq[idx];
        // (max(sqrt(s),1e-12))^2 == max(s, 1e-24) for s >= 0
        g_inv2[idx] = 1.0f / fmaxf(s, 1e-24f);
    }
}

// ---------------- per-row head softmax + S1/S2 accumulation ----------------
// block = 256 threads = 4 groups x 64 threads; 16 rows per block
__global__ void __launch_bounds__(256)
row_softmax_kernel(const void* __restrict__ maskPtr, const float* __restrict__ temp) {
    __shared__ float sT[4][2][8];
    __shared__ float sU[4][2][8];
    __shared__ float accS1[8], accS2[8];
    const int tid = threadIdx.x;
    if (tid < 8) { accS1[tid] = 0.0f; accS2[tid] = 0.0f; }
    __syncthreads();

    const int g = tid >> 6;        // group 0..3
    const int t = tid & 63;        // lane in group
    const int wig = t >> 5;        // warp index within group
    const int lane = t & 31;
    const int mode = g_maskMode;

    for (int rr = 0; rr < 4; rr++) {
        const int row = blockIdx.x * 16 + rr * 4 + g;
        const int b = row >> 13;   // row / 8192
        const float* yrow = g_Y + (size_t)row * CC;
        const float* inv2 = g_inv2 + b * CC;

        float tp[8], up[8];
#pragma unroll
        for (int h = 0; h < 8; h++) {
            float v = yrow[h * 64 + t];
            float sq = v * v;
            tp[h] = sq;
            up[h] = sq * inv2[h * 64 + t];
        }
#pragma unroll
        for (int h = 0; h < 8; h++) {
#pragma unroll
            for (int off = 16; off > 0; off >>= 1) {
                tp[h] += __shfl_xor_sync(0xffffffffu, tp[h], off);
                up[h] += __shfl_xor_sync(0xffffffffu, up[h], off);
            }
        }
        if (lane == 0) {
#pragma unroll
            for (int h = 0; h < 8; h++) { sT[g][wig][h] = tp[h]; sU[g][wig][h] = up[h]; }
        }
        __syncthreads();
        if (t == 0) {
            // mask value for this row
            bool m;
            if (mode == 0)      m = ((const int*)maskPtr)[row] != 0;
            else if (mode == 1) m = ((const unsigned char*)maskPtr)[row] != 0;
            else                m = ((const float*)maskPtr)[row] != 0.0f;

            float T[8], sw[8];
            float mx = -INFINITY;
#pragma unroll
            for (int h = 0; h < 8; h++) {
                T[h] = sT[g][0][h] + sT[g][1][h];
                float U = sU[g][0][h] + sU[g][1][h];
                sw[h] = (m ? U : -1e9f) * temp[h];
                mx = fmaxf(mx, sw[h]);
            }
            float e[8], esum = 0.0f;
#pragma unroll
            for (int h = 0; h < 8; h++) { e[h] = __expf(sw[h] - mx); esum += e[h]; }
            float inv = 1.0f / esum;
#pragma unroll
            for (int h = 0; h < 8; h++) {
                float pi = e[h] * inv;
                g_Pi[(size_t)row * HH + h] = pi;
                atomicAdd(&accS1[h], pi);
                atomicAdd(&accS2[h], pi * T[h]);
            }
        }
        __syncthreads();
    }
    if (tid < 8) {
        int b = (blockIdx.x * 16) >> 13;   // whole block is within one b (8192 % 16 == 0)
        atomicAdd(&g_S1[b * HH + tid], accS1[tid]);
        atomicAdd(&g_S2[b * HH + tid], accS2[tid]);
    }
}

// ---------------- cf = -Pi * attn ----------------
__global__ void __launch_bounds__(256) cf_kernel() {
    size_t idx = (size_t)blockIdx.x * blockDim.x + threadIdx.x;
    if (idx >= (size_t)MM * HH) return;
    int h = (int)(idx & 7);
    int row = (int)(idx >> 3);
    int b = row >> 13;
    float s1 = g_S1[b * HH + h];
    float s2 = g_S2[b * HH + h];
    float dots = s2 / (s1 + 1e-8f);
    float attnNeg = -1.0f / (1.0f + dots);
    g_cf[idx] = g_Pi[idx] * attnNeg;
}

// ---------------- launch ----------------
extern "C" void kernel_launch(void* const* d_in, const int* in_sizes, int n_in,
                              void* d_out, int out_size) {
    const float* x     = (const float*)d_in[0];
    const void*  tmask = (const void*)d_in[1];
    const float* Wqkv  = (const float*)d_in[2];
    const float* temp  = (const float*)d_in[3];
    const float* Wout  = (const float*)d_in[4];
    const float* bout  = (const float*)d_in[5];
    float* out = (float*)d_out;

    float* Y;  cudaGetSymbolAddress((void**)&Y,  g_Y);
    float* cf; cudaGetSymbolAddress((void**)&cf, g_cf);

    // 1) zero accumulators + probe mask dtype
    init_kernel<<<17, 256>>>((const int*)tmask);

    // 2) GEMM1: Y = x @ Wqkv^T   (M=65536, N=K=512)
    {
        dim3 grid(CC / 128, MM / 128);
        sgemm_nt<0><<<grid, 256>>>(x, Wqkv, Y, nullptr, nullptr);
    }

    // 3) column norms over n
    {
        dim3 grid(CC / 128, BB, 8);
        colnorm_accum<<<grid, 256>>>();
        colnorm_finalize<<<(BB * CC + 255) / 256, 256>>>();
    }

    // 4) per-row softmax over heads + S1/S2
    row_softmax_kernel<<<MM / 16, 256>>>(tmask, temp);

    // 5) cf = -Pi * attn
    cf_kernel<<<(MM * HH + 255) / 256, 256>>>();

    // 6) GEMM2: out = (Y * cf) @ Wout^T + bout
    {
        dim3 grid(CC / 128, MM / 128);
        sgemm_nt<1><<<grid, 256>>>(Y, Wout, out, cf, bout);
    }
}

// round 2
// speedup vs baseline: 1.5509x; 1.5509x over previous
#include <cuda_runtime.h>
#include <cuda_bf16.h>
#include <math.h>
#include <stdint.h>

// Problem constants
#define BB 8
#define NN 8192
#define CC 512
#define HH 8
#define DD 64
#define MM (BB * NN)   // 65536 rows

// ---------------- scratch (device globals; no allocation) ----------------
__device__ float g_Y[(size_t)MM * CC];        // 128 MB: Y = x @ Wqkv^T
__device__ float g_sumsq[BB * CC];
__device__ float g_inv2[BB * CC];
__device__ float g_Pi[(size_t)MM * HH];
__device__ float g_S1[BB * HH];
__device__ float g_S2[BB * HH];
__device__ float g_cf[(size_t)MM * HH];
__device__ int   g_maskMode;                  // 0=int32, 1=byte, 2=float32

// ---------------- init + mask-format probe ----------------
__global__ void init_kernel(const int* __restrict__ maskI) {
    int idx = blockIdx.x * blockDim.x + threadIdx.x;
    if (idx < BB * CC) g_sumsq[idx] = 0.0f;
    if (idx < BB * HH) { g_S1[idx] = 0.0f; g_S2[idx] = 0.0f; }
    if (blockIdx.x == 0) {
        __shared__ int okInt, okFloat;
        if (threadIdx.x == 0) { okInt = 1; okFloat = 1; }
        __syncthreads();
        for (int i = threadIdx.x; i < 1024; i += blockDim.x) {
            unsigned int v = ((const unsigned int*)maskI)[i];
            if (!(v == 0u || v == 1u)) atomicAnd(&okInt, 0);
            if (!(v == 0u || v == 0x3F800000u)) atomicAnd(&okFloat, 0);
        }
        __syncthreads();
        if (threadIdx.x == 0) g_maskMode = okInt ? 0 : (okFloat ? 2 : 1);
    }
}

// ---------------- bf16 split-product tensor-core GEMM (NT) ----------------
// C[m,n] = sum_k A[m,k] * B[n,k]
// BM=BN=128, BK=32, 256 threads, 8 warps in 4(m) x 2(n), warp tile 32x64.
// Split each fp32 into hi+lo bf16; C ≈ Ah*Bh + Ah*Bl + Al*Bh.
// APPLY=1: A scaled per-element by cf[m][k>>6]; bias[n] added to C.

#define SMS 40   // smem row stride in bf16 (conflict-free for frag loads)

__device__ __forceinline__ void mma_bf16(float c[4], const uint32_t a[4], const uint32_t b[2]) {
    asm volatile(
        "mma.sync.aligned.m16n8k16.row.col.f32.bf16.bf16.f32 "
        "{%0,%1,%2,%3},{%4,%5,%6,%7},{%8,%9},{%0,%1,%2,%3};\n"
        : "+f"(c[0]), "+f"(c[1]), "+f"(c[2]), "+f"(c[3])
        : "r"(a[0]), "r"(a[1]), "r"(a[2]), "r"(a[3]), "r"(b[0]), "r"(b[1]));
}

template <int APPLY>
__global__ void __launch_bounds__(256, 1)
sgemm_mma(const float* __restrict__ A, const float* __restrict__ B,
          float* __restrict__ C, const float* __restrict__ cf,
          const float* __restrict__ bias) {
    __shared__ __nv_bfloat16 Ah[128][SMS];
    __shared__ __nv_bfloat16 Al[128][SMS];
    __shared__ __nv_bfloat16 Bh[128][SMS];
    __shared__ __nv_bfloat16 Bl[128][SMS];

    const int tid = threadIdx.x;
    const int bm = blockIdx.y * 128;
    const int bn = blockIdx.x * 128;

    const int wid = tid >> 5;
    const int wm = (wid & 3) * 32;    // warp m offset
    const int wn = (wid >> 2) * 64;   // warp n offset
    const int lane = tid & 31;
    const int grp = lane >> 2;        // 0..7
    const int qid = lane & 3;         // 0..3

    // staging assignment: thread -> (row, 16-wide k segment)
    const int lrow = tid >> 1;
    const int lk   = (tid & 1) * 16;
    const float* ag = A + (size_t)(bm + lrow) * CC + lk;
    const float* bg = B + (size_t)(bn + lrow) * CC + lk;

    float acc[2][8][4];
#pragma unroll
    for (int i = 0; i < 2; i++)
#pragma unroll
        for (int j = 0; j < 8; j++)
#pragma unroll
            for (int l = 0; l < 4; l++) acc[i][j][l] = 0.0f;

    float ra[16], rb[16];
    // preload k0 = 0
#pragma unroll
    for (int i = 0; i < 4; i++) {
        *(float4*)&ra[i * 4] = *(const float4*)(ag + i * 4);
        *(float4*)&rb[i * 4] = *(const float4*)(bg + i * 4);
    }

    for (int k0 = 0; k0 < CC; k0 += 32) {
        // apply per-head scale to A (GEMM2) — one head per 16-wide segment
        float s = 1.0f;
        if (APPLY) s = cf[(size_t)(bm + lrow) * HH + ((k0 + lk) >> 6)];
        // convert + store to smem
#pragma unroll
        for (int i = 0; i < 8; i++) {
            float v0 = ra[2 * i], v1 = ra[2 * i + 1];
            if (APPLY) { v0 *= s; v1 *= s; }
            __nv_bfloat16 h0 = __float2bfloat16(v0);
            __nv_bfloat16 h1 = __float2bfloat16(v1);
            __nv_bfloat16 l0 = __float2bfloat16(v0 - __bfloat162float(h0));
            __nv_bfloat16 l1 = __float2bfloat16(v1 - __bfloat162float(h1));
            __nv_bfloat162 ph; ph.x = h0; ph.y = h1;
            __nv_bfloat162 pl; pl.x = l0; pl.y = l1;
            *(__nv_bfloat162*)&Ah[lrow][lk + 2 * i] = ph;
            *(__nv_bfloat162*)&Al[lrow][lk + 2 * i] = pl;

            float w0 = rb[2 * i], w1 = rb[2 * i + 1];
            __nv_bfloat16 g0 = __float2bfloat16(w0);
            __nv_bfloat16 g1 = __float2bfloat16(w1);
            __nv_bfloat16 m0 = __float2bfloat16(w0 - __bfloat162float(g0));
            __nv_bfloat16 m1 = __float2bfloat16(w1 - __bfloat162float(g1));
            __nv_bfloat162 qh; qh.x = g0; qh.y = g1;
            __nv_bfloat162 ql; ql.x = m0; ql.y = m1;
            *(__nv_bfloat162*)&Bh[lrow][lk + 2 * i] = qh;
            *(__nv_bfloat162*)&Bl[lrow][lk + 2 * i] = ql;
        }
        __syncthreads();

        // prefetch next chunk
        if (k0 + 32 < CC) {
#pragma unroll
            for (int i = 0; i < 4; i++) {
                *(float4*)&ra[i * 4] = *(const float4*)(ag + k0 + 32 + i * 4);
                *(float4*)&rb[i * 4] = *(const float4*)(bg + k0 + 32 + i * 4);
            }
        }

        // compute: 2 k-steps of 16
#pragma unroll
        for (int kb = 0; kb < 32; kb += 16) {
            const int kc = kb + 2 * qid;
            uint32_t fah[2][4], fal[2][4], fbh[8][2], fbl[8][2];
#pragma unroll
            for (int mt = 0; mt < 2; mt++) {
                const int r0 = wm + mt * 16 + grp;
                fah[mt][0] = *(const uint32_t*)&Ah[r0][kc];
                fah[mt][1] = *(const uint32_t*)&Ah[r0 + 8][kc];
                fah[mt][2] = *(const uint32_t*)&Ah[r0][kc + 8];
                fah[mt][3] = *(const uint32_t*)&Ah[r0 + 8][kc + 8];
                fal[mt][0] = *(const uint32_t*)&Al[r0][kc];
                fal[mt][1] = *(const uint32_t*)&Al[r0 + 8][kc];
                fal[mt][2] = *(const uint32_t*)&Al[r0][kc + 8];
                fal[mt][3] = *(const uint32_t*)&Al[r0 + 8][kc + 8];
            }
#pragma unroll
            for (int nt = 0; nt < 8; nt++) {
                const int c0 = wn + nt * 8 + grp;
                fbh[nt][0] = *(const uint32_t*)&Bh[c0][kc];
                fbh[nt][1] = *(const uint32_t*)&Bh[c0][kc + 8];
                fbl[nt][0] = *(const uint32_t*)&Bl[c0][kc];
                fbl[nt][1] = *(const uint32_t*)&Bl[c0][kc + 8];
            }
#pragma unroll
            for (int mt = 0; mt < 2; mt++)
#pragma unroll
                for (int nt = 0; nt < 8; nt++) {
                    mma_bf16(acc[mt][nt], fah[mt], fbh[nt]);
                    mma_bf16(acc[mt][nt], fah[mt], fbl[nt]);
                    mma_bf16(acc[mt][nt], fal[mt], fbh[nt]);
                }
        }
        __syncthreads();
    }

    // epilogue
#pragma unroll
    for (int mt = 0; mt < 2; mt++) {
#pragma unroll
        for (int nt = 0; nt < 8; nt++) {
            int row = bm + wm + mt * 16 + grp;
            int col = bn + wn + nt * 8 + 2 * qid;
            float2 v0 = make_float2(acc[mt][nt][0], acc[mt][nt][1]);
            float2 v1 = make_float2(acc[mt][nt][2], acc[mt][nt][3]);
            if (APPLY) {
                v0.x += bias[col]; v0.y += bias[col + 1];
                v1.x += bias[col]; v1.y += bias[col + 1];
            }
            *(float2*)(C + (size_t)row * CC + col) = v0;
            *(float2*)(C + (size_t)(row + 8) * CC + col) = v1;
        }
    }
}

// ---------------- column sum-of-squares over n ----------------
__global__ void __launch_bounds__(256) colnorm_accum() {
    __shared__ float s[256];
    const int cx = threadIdx.x & 127;
    const int ny = threadIdx.x >> 7;
    const int c0 = blockIdx.x * 128;
    const int b = blockIdx.y;
    const int n0 = blockIdx.z * 1024;
    const float* base = g_Y + ((size_t)b * NN) * CC + c0 + cx;
    float acc = 0.0f;
    for (int n = n0 + ny; n < n0 + 1024; n += 2) {
        float v = base[(size_t)n * CC];
        acc = fmaf(v, v, acc);
    }
    s[threadIdx.x] = acc;
    __syncthreads();
    if (threadIdx.x < 128) {
        float tot = s[threadIdx.x] + s[threadIdx.x + 128];
        atomicAdd(&g_sumsq[b * CC + c0 + cx], tot);
    }
}

__global__ void colnorm_finalize() {
    int idx = blockIdx.x * blockDim.x + threadIdx.x;
    if (idx < BB * CC) {
        float s = g_sumsq[idx];
        g_inv2[idx] = 1.0f / fmaxf(s, 1e-24f);
    }
}

// ---------------- per-row head softmax + S1/S2 accumulation ----------------
__global__ void __launch_bounds__(256)
row_softmax_kernel(const void* __restrict__ maskPtr, const float* __restrict__ temp) {
    __shared__ float sT[4][2][8];
    __shared__ float sU[4][2][8];
    __shared__ float accS1[8], accS2[8];
    const int tid = threadIdx.x;
    if (tid < 8) { accS1[tid] = 0.0f; accS2[tid] = 0.0f; }
    __syncthreads();

    const int g = tid >> 6;
    const int t = tid & 63;
    const int wig = t >> 5;
    const int lane = t & 31;
    const int mode = g_maskMode;

    for (int rr = 0; rr < 4; rr++) {
        const int row = blockIdx.x * 16 + rr * 4 + g;
        const int b = row >> 13;
        const float* yrow = g_Y + (size_t)row * CC;
        const float* inv2 = g_inv2 + b * CC;

        float tp[8], up[8];
#pragma unroll
        for (int h = 0; h < 8; h++) {
            float v = yrow[h * 64 + t];
            float sq = v * v;
            tp[h] = sq;
            up[h] = sq * inv2[h * 64 + t];
        }
#pragma unroll
        for (int h = 0; h < 8; h++) {
#pragma unroll
            for (int off = 16; off > 0; off >>= 1) {
                tp[h] += __shfl_xor_sync(0xffffffffu, tp[h], off);
                up[h] += __shfl_xor_sync(0xffffffffu, up[h], off);
            }
        }
        if (lane == 0) {
#pragma unroll
            for (int h = 0; h < 8; h++) { sT[g][wig][h] = tp[h]; sU[g][wig][h] = up[h]; }
        }
        __syncthreads();
        if (t == 0) {
            bool m;
            if (mode == 0)      m = ((const int*)maskPtr)[row] != 0;
            else if (mode == 1) m = ((const unsigned char*)maskPtr)[row] != 0;
            else                m = ((const float*)maskPtr)[row] != 0.0f;

            float T[8], sw[8];
            float mx = -INFINITY;
#pragma unroll
            for (int h = 0; h < 8; h++) {
                T[h] = sT[g][0][h] + sT[g][1][h];
                float U = sU[g][0][h] + sU[g][1][h];
                sw[h] = (m ? U : -1e9f) * temp[h];
                mx = fmaxf(mx, sw[h]);
            }
            float e[8], esum = 0.0f;
#pragma unroll
            for (int h = 0; h < 8; h++) { e[h] = __expf(sw[h] - mx); esum += e[h]; }
            float inv = 1.0f / esum;
#pragma unroll
            for (int h = 0; h < 8; h++) {
                float pi = e[h] * inv;
                g_Pi[(size_t)row * HH + h] = pi;
                atomicAdd(&accS1[h], pi);
                atomicAdd(&accS2[h], pi * T[h]);
            }
        }
        __syncthreads();
    }
    if (tid < 8) {
        int b = (blockIdx.x * 16) >> 13;
        atomicAdd(&g_S1[b * HH + tid], accS1[tid]);
        atomicAdd(&g_S2[b * HH + tid], accS2[tid]);
    }
}

// ---------------- cf = -Pi * attn ----------------
__global__ void __launch_bounds__(256) cf_kernel() {
    size_t idx = (size_t)blockIdx.x * blockDim.x + threadIdx.x;
    if (idx >= (size_t)MM * HH) return;
    int h = (int)(idx & 7);
    int row = (int)(idx >> 3);
    int b = row >> 13;
    float s1 = g_S1[b * HH + h];
    float s2 = g_S2[b * HH + h];
    float dots = s2 / (s1 + 1e-8f);
    float attnNeg = -1.0f / (1.0f + dots);
    g_cf[idx] = g_Pi[idx] * attnNeg;
}

// ---------------- launch ----------------
extern "C" void kernel_launch(void* const* d_in, const int* in_sizes, int n_in,
                              void* d_out, int out_size) {
    const float* x     = (const float*)d_in[0];
    const void*  tmask = (const void*)d_in[1];
    const float* Wqkv  = (const float*)d_in[2];
    const float* temp  = (const float*)d_in[3];
    const float* Wout  = (const float*)d_in[4];
    const float* bout  = (const float*)d_in[5];
    float* out = (float*)d_out;

    float* Y;  cudaGetSymbolAddress((void**)&Y,  g_Y);
    float* cf; cudaGetSymbolAddress((void**)&cf, g_cf);

    init_kernel<<<17, 256>>>((const int*)tmask);

    // GEMM1: Y = x @ Wqkv^T
    {
        dim3 grid(CC / 128, MM / 128);
        sgemm_mma<0><<<grid, 256>>>(x, Wqkv, Y, nullptr, nullptr);
    }

    // column norms
    {
        dim3 grid(CC / 128, BB, 8);
        colnorm_accum<<<grid, 256>>>();
        colnorm_finalize<<<(BB * CC + 255) / 256, 256>>>();
    }

    // softmax + S1/S2
    row_softmax_kernel<<<MM / 16, 256>>>(tmask, temp);

    // cf
    cf_kernel<<<(MM * HH + 255) / 256, 256>>>();

    // GEMM2: out = (Y * cf) @ Wout^T + bout
    {
        dim3 grid(CC / 128, MM / 128);
        sgemm_mma<1><<<grid, 256>>>(Y, Wout, out, cf, bout);
    }
}